// round 4
// baseline (speedup 1.0000x reference)
#include <cuda_runtime.h>

// Fused per-graph GNN, round 4 (= round 3 resubmit after infra failure):
// row-pair FFMA2 + col-major activations, 2 graphs per block (weight regs
// reused), 8-lane logit subgroups.

typedef unsigned long long u64;

__device__ __forceinline__ void ffma2(u64& d, u64 a, u64 b) {
    asm("fma.rn.f32x2 %0, %1, %2, %0;" : "+l"(d) : "l"(a), "l"(b));
}
__device__ __forceinline__ u64 fadd2(u64 a, u64 b) {
    u64 d; asm("add.rn.f32x2 %0, %1, %2;" : "=l"(d) : "l"(a), "l"(b)); return d;
}
__device__ __forceinline__ u64 pack2(float v) {
    u64 d; asm("mov.b64 %0, {%1, %1};" : "=l"(d) : "f"(v)); return d;
}

namespace {
constexpr int NPH = 10;
constexpr int Hd  = 128;
constexpr int CDm = 32;
constexpr int TPB = 256;
constexpr int G   = 2;      // graphs per block
constexpr int RWS = 20;     // rows per block = G*NPH

// smem offsets (floats). x buffers are col-major [k][20] (stride 20).
constexpr int OFF_XM   = 0;        // 2560
constexpr int OFF_XO   = 2560;
constexpr int OFF_NM   = 5120;
constexpr int OFF_NO   = 7680;
constexpr int OFF_A    = 10240;    // 10240: XL / CG F bufs / linear stage / enc stage
constexpr int OFF_B    = 20480;    // 10240: XR
constexpr int OFF_ATT  = 30720;    // 512
constexpr int OFF_LOG  = 31232;    // 2*40*16 = 1280
constexpr int OFF_POOL = 32512;    // 512
constexpr int OFF_RED  = 33024;    // 256
constexpr int SMEM_FLOATS = 33280;
constexpr int SMEM_BYTES  = SMEM_FLOATS * 4;
}

// ======================= GATv2 relation =======================
// src/dst col-major [k][20]. XL/XR pair-interleaved: [p][col 0..511][par].
__device__ __forceinline__ void gatv2_block(
    const float* __restrict__ s_src, const float* __restrict__ s_dst,
    const float* __restrict__ Wl, const float* __restrict__ Wr,
    const float* __restrict__ att, const float* __restrict__ bias,
    float* s_XL, float* s_XR, float* s_att, float* s_log,
    float* s_out, bool accum)
{
    const int t = threadIdx.x;

    // stage att (512 floats)
    for (int idx = t; idx < 512; idx += TPB) s_att[idx] = att[idx];

    // ---- GEMMs: XL = src@Wl (warps 0-3), XR = dst@Wr (warps 4-7), 4 cols/thread
    {
        const bool isL = (t < 128);
        const int c4 = (t & 127) * 4;
        const float* __restrict__ W  = isL ? Wl : Wr;
        const float* __restrict__ xb = isL ? s_src : s_dst;
        u64 acc[10][4];
#pragma unroll
        for (int p = 0; p < 10; p++)
#pragma unroll
            for (int q = 0; q < 4; q++) acc[p][q] = 0ull;
#pragma unroll 2
        for (int k = 0; k < Hd; k++) {
            const ulonglong2 xa = *(const ulonglong2*)&xb[k*RWS + 0];
            const ulonglong2 xc = *(const ulonglong2*)&xb[k*RWS + 4];
            const ulonglong2 xe = *(const ulonglong2*)&xb[k*RWS + 8];
            const ulonglong2 xg = *(const ulonglong2*)&xb[k*RWS + 12];
            const ulonglong2 xi = *(const ulonglong2*)&xb[k*RWS + 16];
            const float4 wv = *(const float4*)&W[k*512 + c4];
            const u64 w0 = pack2(wv.x), w1 = pack2(wv.y);
            const u64 w2 = pack2(wv.z), w3 = pack2(wv.w);
            u64 xp[10] = {xa.x, xa.y, xc.x, xc.y, xe.x, xe.y, xg.x, xg.y, xi.x, xi.y};
#pragma unroll
            for (int p = 0; p < 10; p++) {
                ffma2(acc[p][0], xp[p], w0);
                ffma2(acc[p][1], xp[p], w1);
                ffma2(acc[p][2], xp[p], w2);
                ffma2(acc[p][3], xp[p], w3);
            }
        }
        float* outp = isL ? s_XL : s_XR;
#pragma unroll
        for (int p = 0; p < 10; p++)
#pragma unroll
            for (int q = 0; q < 4; q++)
                *(u64*)&outp[p*1024 + (c4 + q)*2] = acc[p][q];
    }
    __syncthreads();

    // ---- logits: 8-lane subgroups, 4 tasks/warp. 80 tasks = 2 graphs x (h,j)
    {
        const int warp = t >> 5, lane = t & 31;
        const int sub = lane >> 3, l8 = lane & 7;
#pragma unroll 1
        for (int rr = 0; rr < 3; rr++) {
            const int task = rr*32 + warp*4 + sub;
            if (task < 80) {
                const int g = task / 40;
                const int hj = task % 40;
                const int h = hj / 10, j = hj % 10;
                const int jp = j >> 1, pj = j & 1;
                float s[10];
#pragma unroll
                for (int i = 0; i < 10; i++) s[i] = 0.f;
#pragma unroll
                for (int cc = 0; cc < 4; cc++) {
                    const int c = l8*4 + cc*32;
                    const int cbase = (h*128 + c)*2;
                    const float4 r0 = *(const float4*)&s_XR[(g*5 + jp)*1024 + cbase];
                    const float4 r1 = *(const float4*)&s_XR[(g*5 + jp)*1024 + cbase + 4];
                    const float xr0 = pj ? r0.y : r0.x;
                    const float xr1 = pj ? r0.w : r0.z;
                    const float xr2 = pj ? r1.y : r1.x;
                    const float xr3 = pj ? r1.w : r1.z;
                    const float4 at = *(const float4*)&s_att[h*128 + c];
#pragma unroll
                    for (int ip = 0; ip < 5; ip++) {
                        const float4 a = *(const float4*)&s_XL[(g*5 + ip)*1024 + cbase];
                        const float4 b = *(const float4*)&s_XL[(g*5 + ip)*1024 + cbase + 4];
                        float e0 = a.x + xr0;
                        float e1 = a.z + xr1;
                        float e2 = b.x + xr2;
                        float e3 = b.z + xr3;
                        float v =        at.x * fmaf(e0, 0.6f, 0.4f*fabsf(e0));
                        v = fmaf(at.y, fmaf(e1, 0.6f, 0.4f*fabsf(e1)), v);
                        v = fmaf(at.z, fmaf(e2, 0.6f, 0.4f*fabsf(e2)), v);
                        v = fmaf(at.w, fmaf(e3, 0.6f, 0.4f*fabsf(e3)), v);
                        s[2*ip] += v;
                        e0 = a.y + xr0;
                        e1 = a.w + xr1;
                        e2 = b.y + xr2;
                        e3 = b.w + xr3;
                        v =        at.x * fmaf(e0, 0.6f, 0.4f*fabsf(e0));
                        v = fmaf(at.y, fmaf(e1, 0.6f, 0.4f*fabsf(e1)), v);
                        v = fmaf(at.z, fmaf(e2, 0.6f, 0.4f*fabsf(e2)), v);
                        v = fmaf(at.w, fmaf(e3, 0.6f, 0.4f*fabsf(e3)), v);
                        s[2*ip+1] += v;
                    }
                }
#pragma unroll
                for (int i = 0; i < 10; i++) {
                    s[i] += __shfl_xor_sync(0xffffffffu, s[i], 4);
                    s[i] += __shfl_xor_sync(0xffffffffu, s[i], 2);
                    s[i] += __shfl_xor_sync(0xffffffffu, s[i], 1);
                }
                if (l8 == 0) {
#pragma unroll
                    for (int i = 0; i < 10; i++) s_log[g*640 + hj*16 + i] = s[i];
                }
            }
        }
    }
    __syncthreads();

    // ---- softmax over i per (g,h,j) ----
    if (t < 80) {
        float* lg = s_log + (t / 40)*640 + (t % 40)*16;
        float m = lg[0];
#pragma unroll
        for (int i = 1; i < 10; i++) m = fmaxf(m, lg[i]);
        float a[10]; float sum = 0.f;
#pragma unroll
        for (int i = 0; i < 10; i++) { a[i] = __expf(lg[i] - m); sum += a[i]; }
        const float inv = __fdividef(1.f, sum);
#pragma unroll
        for (int i = 0; i < 10; i++) lg[i] = a[i] * inv;
    }
    __syncthreads();

    // ---- aggregate: out[j,c] = bias + 0.25 * sum_h sum_i alpha*XL ----
    {
        const int c = t & 127, rh = t >> 7;
        const float bv = bias[c];
#pragma unroll 1
        for (int g = 0; g < G; g++) {
            float accj[5] = {0.f, 0.f, 0.f, 0.f, 0.f};
#pragma unroll
            for (int h = 0; h < 4; h++) {
                float xlh[10];
#pragma unroll
                for (int ip = 0; ip < 5; ip++) {
                    const float2 xp2 = *(const float2*)&s_XL[(g*5 + ip)*1024 + (h*128 + c)*2];
                    xlh[2*ip] = xp2.x; xlh[2*ip+1] = xp2.y;
                }
#pragma unroll
                for (int jj = 0; jj < 5; jj++) {
                    const float* al = s_log + g*640 + (h*10 + rh*5 + jj)*16;
                    const float4 a0 = *(const float4*)al;
                    const float4 a1 = *(const float4*)(al + 4);
                    const float2 a2 = *(const float2*)(al + 8);
                    float v = accj[jj];
                    v = fmaf(a0.x, xlh[0], v); v = fmaf(a0.y, xlh[1], v);
                    v = fmaf(a0.z, xlh[2], v); v = fmaf(a0.w, xlh[3], v);
                    v = fmaf(a1.x, xlh[4], v); v = fmaf(a1.y, xlh[5], v);
                    v = fmaf(a1.z, xlh[6], v); v = fmaf(a1.w, xlh[7], v);
                    v = fmaf(a2.x, xlh[8], v); v = fmaf(a2.y, xlh[9], v);
                    accj[jj] = v;
                }
            }
#pragma unroll
            for (int jj = 0; jj < 5; jj++) {
                const int r = g*10 + rh*5 + jj;
                float v = accj[jj]*0.25f + bv;
                if (accum) v += s_out[c*RWS + r];
                s_out[c*RWS + r] = v;
            }
        }
    }
    __syncthreads();
}

// ======================= CGConv relation =======================
// F bufs in s_F: Fd@0, Fs@2560, Sd@5120, Ss@7680; pair-interleaved [p][c][par]
__device__ __forceinline__ void cgconv_block(
    const float* __restrict__ s_src, const float* __restrict__ s_dst,
    const float* __restrict__ Wf, const float* __restrict__ bf,
    const float* __restrict__ Ws, const float* __restrict__ bs,
    float* s_F, float* s_out, bool accum)
{
    const int t = threadIdx.x;
    {
        const int fs   = t >> 7;            // 0: f-branch, 1: s-branch
        const int half = (t >> 6) & 1;      // 0: dst rows of W, 1: src rows
        const int c2   = (t & 63) * 2;
        const float* __restrict__ W  = (fs ? Ws : Wf) + half*Hd*Hd;
        const float* __restrict__ xb = half ? s_src : s_dst;
        u64 acc[10][2];
#pragma unroll
        for (int p = 0; p < 10; p++) { acc[p][0] = 0ull; acc[p][1] = 0ull; }
#pragma unroll 2
        for (int k = 0; k < Hd; k++) {
            const ulonglong2 xa = *(const ulonglong2*)&xb[k*RWS + 0];
            const ulonglong2 xc = *(const ulonglong2*)&xb[k*RWS + 4];
            const ulonglong2 xe = *(const ulonglong2*)&xb[k*RWS + 8];
            const ulonglong2 xg = *(const ulonglong2*)&xb[k*RWS + 12];
            const ulonglong2 xi = *(const ulonglong2*)&xb[k*RWS + 16];
            const float2 wv = *(const float2*)&W[k*Hd + c2];
            const u64 w0 = pack2(wv.x), w1 = pack2(wv.y);
            u64 xp[10] = {xa.x, xa.y, xc.x, xc.y, xe.x, xe.y, xg.x, xg.y, xi.x, xi.y};
#pragma unroll
            for (int p = 0; p < 10; p++) {
                ffma2(acc[p][0], xp[p], w0);
                ffma2(acc[p][1], xp[p], w1);
            }
        }
        if (half == 0) {   // fold bias into dst half
            const float* bb = fs ? bs : bf;
            const u64 b0 = pack2(bb[c2]), b1 = pack2(bb[c2+1]);
#pragma unroll
            for (int p = 0; p < 10; p++) {
                acc[p][0] = fadd2(acc[p][0], b0);
                acc[p][1] = fadd2(acc[p][1], b1);
            }
        }
        float* F = s_F + fs*5120 + half*2560;
#pragma unroll
        for (int p = 0; p < 10; p++) {
            *(u64*)&F[p*256 + c2*2]       = acc[p][0];
            *(u64*)&F[p*256 + (c2+1)*2]   = acc[p][1];
        }
    }
    __syncthreads();

    // ---- elementwise: out_i = x_i + sum_j sigmoid(Fd_i+Fs_j)*softplus(Sd_i+Ss_j)
    {
        const int c = t & 127, rh = t >> 7;
        const float* Fd = s_F;
        const float* Fs = s_F + 2560;
        const float* Sd = s_F + 5120;
        const float* Ss = s_F + 7680;
#pragma unroll 1
        for (int g = 0; g < G; g++) {
            float fsv[10], ssv[10];
#pragma unroll
            for (int jp = 0; jp < 5; jp++) {
                const float2 f2 = *(const float2*)&Fs[(g*5 + jp)*256 + c*2];
                const float2 s2 = *(const float2*)&Ss[(g*5 + jp)*256 + c*2];
                fsv[2*jp] = f2.x; fsv[2*jp+1] = f2.y;
                ssv[2*jp] = s2.x; ssv[2*jp+1] = s2.y;
            }
#pragma unroll
            for (int jj = 0; jj < 5; jj++) {
                const int i = rh*5 + jj;
                const int r = g*10 + i;
                const float fd = Fd[(g*5 + (i>>1))*256 + c*2 + (i&1)];
                const float sd = Sd[(g*5 + (i>>1))*256 + c*2 + (i&1)];
                float acc = s_dst[c*RWS + r];   // residual
#pragma unroll
                for (int j = 0; j < 10; j++) {
                    const float f = fd + fsv[j];
                    const float s = sd + ssv[j];
                    const float sig = __fdividef(1.f, 1.f + __expf(-f));
                    const float sp  = fmaxf(s, 0.f) + __logf(1.f + __expf(-fabsf(s)));
                    acc = fmaf(sig, sp, acc);
                }
                if (accum) acc += s_out[c*RWS + r];
                s_out[c*RWS + r] = acc;
            }
        }
    }
    __syncthreads();
}

// ======================= node linear (both matrices, split-k=2) ===============
__device__ __forceinline__ void dual_linear_block(
    const float* __restrict__ s_nm, const float* __restrict__ s_no,
    const float* __restrict__ W, const float* __restrict__ b,
    float* s_xm, float* s_xo, float* s_stage /* u64 capacity 2560 */)
{
    const int t = threadIdx.x;
    const int kh  = t >> 7;
    const int sel = (t >> 6) & 1;
    const int c2  = (t & 63) * 2;
    const int id  = sel*64 + (t & 63);
    const float* __restrict__ xb = sel ? s_no : s_nm;
    u64 acc[10][2];
#pragma unroll
    for (int p = 0; p < 10; p++) { acc[p][0] = 0ull; acc[p][1] = 0ull; }
    const int kbase = kh * 64;
#pragma unroll 2
    for (int kk = 0; kk < 64; kk++) {
        const int k = kbase + kk;
        const ulonglong2 xa = *(const ulonglong2*)&xb[k*RWS + 0];
        const ulonglong2 xc = *(const ulonglong2*)&xb[k*RWS + 4];
        const ulonglong2 xe = *(const ulonglong2*)&xb[k*RWS + 8];
        const ulonglong2 xg = *(const ulonglong2*)&xb[k*RWS + 12];
        const ulonglong2 xi = *(const ulonglong2*)&xb[k*RWS + 16];
        const float2 wv = *(const float2*)&W[k*Hd + c2];
        const u64 w0 = pack2(wv.x), w1 = pack2(wv.y);
        u64 xp[10] = {xa.x, xa.y, xc.x, xc.y, xe.x, xe.y, xg.x, xg.y, xi.x, xi.y};
#pragma unroll
        for (int p = 0; p < 10; p++) {
            ffma2(acc[p][0], xp[p], w0);
            ffma2(acc[p][1], xp[p], w1);
        }
    }
    u64* stage = (u64*)s_stage;
    if (kh == 1) {
#pragma unroll
        for (int p = 0; p < 10; p++) {
            stage[id*20 + p*2 + 0] = acc[p][0];
            stage[id*20 + p*2 + 1] = acc[p][1];
        }
    }
    __syncthreads();
    if (kh == 0) {
        const u64 b0 = pack2(b[c2]), b1 = pack2(b[c2+1]);
        float* outp = sel ? s_xo : s_xm;
#pragma unroll
        for (int p = 0; p < 10; p++) {
            const u64 v0 = fadd2(fadd2(acc[p][0], stage[id*20 + p*2 + 0]), b0);
            const u64 v1 = fadd2(fadd2(acc[p][1], stage[id*20 + p*2 + 1]), b1);
            *(u64*)&outp[c2*RWS + 2*p]     = v0;   // rows 2p,2p+1 of col c2
            *(u64*)&outp[(c2+1)*RWS + 2*p] = v1;
        }
    }
    __syncthreads();
}

extern "C" __global__ void __launch_bounds__(TPB, 1)
yomi_kernel(
    const float* __restrict__ x_my,  const float* __restrict__ x_opp,
    const float* __restrict__ W_enc, const float* __restrict__ b_enc,
    const float* __restrict__ gb_Wl, const float* __restrict__ gb_Wr,
    const float* __restrict__ gb_att,const float* __restrict__ gb_b,
    const float* __restrict__ gr_Wl, const float* __restrict__ gr_Wr,
    const float* __restrict__ gr_att,const float* __restrict__ gr_b,
    const float* __restrict__ cl_Wf, const float* __restrict__ cl_bf,
    const float* __restrict__ cl_Ws, const float* __restrict__ cl_bs,
    const float* __restrict__ cr_Wf, const float* __restrict__ cr_bf,
    const float* __restrict__ cr_Ws, const float* __restrict__ cr_bs,
    const float* __restrict__ node_W,const float* __restrict__ node_b,
    const float* __restrict__ W1,    const float* __restrict__ b1,
    const float* __restrict__ W2,    const float* __restrict__ b2,
    float* __restrict__ out)
{
    extern __shared__ float sm[];
    float* s_xm  = sm + OFF_XM;
    float* s_xo  = sm + OFF_XO;
    float* s_nm  = sm + OFF_NM;
    float* s_no  = sm + OFF_NO;
    float* s_A   = sm + OFF_A;
    float* s_B   = sm + OFF_B;
    float* s_att = sm + OFF_ATT;
    float* s_log = sm + OFF_LOG;
    float* s_pool= sm + OFF_POOL;
    float* s_red = sm + OFF_RED;

    const int blk = blockIdx.x;
    const int t = threadIdx.x;

    // ---- encoder: stage transposed raw x, then [20,32]@[32,128]+b per matrix
    {
        for (int idx = t; idx < 2*RWS*CDm; idx += TPB) {
            const int m = idx / (RWS*CDm);
            const int rem = idx - m*RWS*CDm;
            const int r20 = rem / CDm, k = rem % CDm;
            const float v = (m ? x_opp : x_my)[(blk*RWS + r20)*CDm + k];
            s_A[m*640 + k*RWS + r20] = v;
        }
        __syncthreads();
        const int c = t & 127, m = t >> 7;
        const float* xb = s_A + m*640;
        u64 acc[10];
#pragma unroll
        for (int p = 0; p < 10; p++) acc[p] = 0ull;
#pragma unroll 4
        for (int k = 0; k < CDm; k++) {
            const ulonglong2 xa = *(const ulonglong2*)&xb[k*RWS + 0];
            const ulonglong2 xc = *(const ulonglong2*)&xb[k*RWS + 4];
            const ulonglong2 xe = *(const ulonglong2*)&xb[k*RWS + 8];
            const ulonglong2 xg = *(const ulonglong2*)&xb[k*RWS + 12];
            const ulonglong2 xi = *(const ulonglong2*)&xb[k*RWS + 16];
            const u64 w = pack2(W_enc[k*Hd + c]);
            u64 xp[10] = {xa.x, xa.y, xc.x, xc.y, xe.x, xe.y, xg.x, xg.y, xi.x, xi.y};
#pragma unroll
            for (int p = 0; p < 10; p++) ffma2(acc[p], xp[p], w);
        }
        const u64 bv = pack2(b_enc[c]);
        float* outp = m ? s_xo : s_xm;
#pragma unroll
        for (int p = 0; p < 10; p++)
            *(u64*)&outp[c*RWS + 2*p] = fadd2(acc[p], bv);
        __syncthreads();
    }

    // ---- 2 hetero layers ----
#pragma unroll 1
    for (int l = 0; l < 2; l++) {
        const int wG = l * Hd * 512;
        const int wC = l * 2*Hd * Hd;
        const int wN = l * Hd * Hd;
        const int wb = l * Hd;
        gatv2_block(s_xm, s_xo, gb_Wl + wG, gb_Wr + wG, gb_att + l*4*Hd,
                    gb_b + wb, s_A, s_B, s_att, s_log, s_no, false);
        cgconv_block(s_xm, s_xo, cl_Wf + wC, cl_bf + wb, cl_Ws + wC, cl_bs + wb,
                     s_A, s_no, true);
        cgconv_block(s_xo, s_xm, cr_Wf + wC, cr_bf + wb, cr_Ws + wC, cr_bs + wb,
                     s_A, s_nm, false);
        gatv2_block(s_xo, s_xm, gr_Wl + wG, gr_Wr + wG, gr_att + l*4*Hd,
                    gr_b + wb, s_A, s_B, s_att, s_log, s_nm, true);
        dual_linear_block(s_nm, s_no, node_W + wN, node_b + wb, s_xm, s_xo, s_A);
    }

    // ---- pool + MLP head (per graph) ----
    {
        const int c = t & 127, m = t >> 7;
        const float* xb = m ? s_xo : s_xm;
#pragma unroll
        for (int g = 0; g < G; g++) {
            float p = 0.f;
#pragma unroll
            for (int r = 0; r < NPH; r++) p += xb[c*RWS + g*NPH + r];
            s_pool[g*256 + m*128 + c] = p * 0.1f;
        }
    }
    __syncthreads();
    {
        const int c = t & 127, g = t >> 7;
        float a = 0.f;
#pragma unroll 4
        for (int k = 0; k < 256; k++)
            a = fmaf(s_pool[g*256 + k], W1[k*Hd + c], a);
        float hv = a + b1[c];
        hv = (hv >= 0.f) ? hv : 128.f * hv;   // LeakyReLU slope = final_dim
        s_red[t] = hv * W2[c];
    }
    __syncthreads();
    if (t < 64) {
        const int g = t >> 5, lane = t & 31;
        float v = s_red[g*128 + lane] + s_red[g*128 + lane + 32]
                + s_red[g*128 + lane + 64] + s_red[g*128 + lane + 96];
#pragma unroll
        for (int o = 16; o > 0; o >>= 1) v += __shfl_xor_sync(0xffffffffu, v, o);
        if (lane == 0) out[blk*G + g] = v + b2[0];
    }
}

extern "C" void kernel_launch(void* const* d_in, const int* in_sizes, int n_in,
                              void* d_out, int out_size)
{
    const float* x_my   = (const float*)d_in[0];
    const float* x_opp  = (const float*)d_in[1];
    const float* W_enc  = (const float*)d_in[2];
    const float* b_enc  = (const float*)d_in[3];
    const float* gb_Wl  = (const float*)d_in[4];
    const float* gb_Wr  = (const float*)d_in[5];
    const float* gb_att = (const float*)d_in[6];
    const float* gb_b   = (const float*)d_in[7];
    const float* gr_Wl  = (const float*)d_in[8];
    const float* gr_Wr  = (const float*)d_in[9];
    const float* gr_att = (const float*)d_in[10];
    const float* gr_b   = (const float*)d_in[11];
    const float* cl_Wf  = (const float*)d_in[12];
    const float* cl_bf  = (const float*)d_in[13];
    const float* cl_Ws  = (const float*)d_in[14];
    const float* cl_bs  = (const float*)d_in[15];
    const float* cr_Wf  = (const float*)d_in[16];
    const float* cr_bf  = (const float*)d_in[17];
    const float* cr_Ws  = (const float*)d_in[18];
    const float* cr_bs  = (const float*)d_in[19];
    const float* node_W = (const float*)d_in[20];
    const float* node_b = (const float*)d_in[21];
    const float* W1     = (const float*)d_in[22];
    const float* b1     = (const float*)d_in[23];
    const float* W2     = (const float*)d_in[24];
    const float* b2     = (const float*)d_in[25];

    const int n_nodes = in_sizes[0] / CDm;   // N = B * NPH
    const int nblocks = n_nodes / (NPH * G); // B / 2

    cudaFuncSetAttribute(yomi_kernel,
                         cudaFuncAttributeMaxDynamicSharedMemorySize, SMEM_BYTES);

    yomi_kernel<<<nblocks, TPB, SMEM_BYTES>>>(
        x_my, x_opp, W_enc, b_enc,
        gb_Wl, gb_Wr, gb_att, gb_b,
        gr_Wl, gr_Wr, gr_att, gr_b,
        cl_Wf, cl_bf, cl_Ws, cl_bs,
        cr_Wf, cr_bf, cr_Ws, cr_bs,
        node_W, node_b, W1, b1, W2, b2,
        (float*)d_out);
}

// round 5
// speedup vs baseline: 1.0295x; 1.0295x over previous
#include <cuda_runtime.h>

// Fused per-graph GNN, round 5: same algorithm/layout as round 4 (row-pair
// FFMA2, col-major activations, 2 graphs/block) but TPB=512 so 16 warps/SM
// hide latency (round 4 was issue-bound at 8 warps/SM).

typedef unsigned long long u64;

__device__ __forceinline__ void ffma2(u64& d, u64 a, u64 b) {
    asm("fma.rn.f32x2 %0, %1, %2, %0;" : "+l"(d) : "l"(a), "l"(b));
}
__device__ __forceinline__ u64 fadd2(u64 a, u64 b) {
    u64 d; asm("add.rn.f32x2 %0, %1, %2;" : "=l"(d) : "l"(a), "l"(b)); return d;
}
__device__ __forceinline__ u64 pack2(float v) {
    u64 d; asm("mov.b64 %0, {%1, %1};" : "=l"(d) : "f"(v)); return d;
}

namespace {
constexpr int NPH = 10;
constexpr int Hd  = 128;
constexpr int CDm = 32;
constexpr int TPB = 512;
constexpr int G   = 2;      // graphs per block
constexpr int RWS = 20;     // rows per block = G*NPH

// smem offsets (floats). x buffers are col-major [k][20] (stride 20).
constexpr int OFF_XM   = 0;        // 2560
constexpr int OFF_XO   = 2560;
constexpr int OFF_NM   = 5120;
constexpr int OFF_NO   = 7680;
constexpr int OFF_A    = 10240;    // 10240: XL / CG F bufs / linear stage / enc stage
constexpr int OFF_B    = 20480;    // 10240: XR
constexpr int OFF_ATT  = 30720;    // 512
constexpr int OFF_LOG  = 31232;    // 2*40*16 = 1280
constexpr int OFF_POOL = 32512;    // 512
constexpr int OFF_RED  = 33024;    // 512
constexpr int SMEM_FLOATS = 33536;
constexpr int SMEM_BYTES  = SMEM_FLOATS * 4;
}

// ======================= GATv2 relation =======================
// src/dst col-major [k][20]. XL/XR pair-interleaved: [p][col 0..511][par].
__device__ __forceinline__ void gatv2_block(
    const float* __restrict__ s_src, const float* __restrict__ s_dst,
    const float* __restrict__ Wl, const float* __restrict__ Wr,
    const float* __restrict__ att, const float* __restrict__ bias,
    float* s_XL, float* s_XR, float* s_att, float* s_log,
    float* s_out, bool accum)
{
    const int t = threadIdx.x;

    // stage att (512 floats, one per thread)
    s_att[t] = att[t];

    // ---- GEMMs: XL = src@Wl (t<256), XR = dst@Wr (t>=256); 2 cols/thread ----
    {
        const bool isL = (t < 256);
        const int c2 = (t & 255) * 2;
        const float* __restrict__ W  = isL ? Wl : Wr;
        const float* __restrict__ xb = isL ? s_src : s_dst;
        u64 acc[10][2];
#pragma unroll
        for (int p = 0; p < 10; p++) { acc[p][0] = 0ull; acc[p][1] = 0ull; }
#pragma unroll 2
        for (int k = 0; k < Hd; k++) {
            const ulonglong2 xa = *(const ulonglong2*)&xb[k*RWS + 0];
            const ulonglong2 xc = *(const ulonglong2*)&xb[k*RWS + 4];
            const ulonglong2 xe = *(const ulonglong2*)&xb[k*RWS + 8];
            const ulonglong2 xg = *(const ulonglong2*)&xb[k*RWS + 12];
            const ulonglong2 xi = *(const ulonglong2*)&xb[k*RWS + 16];
            const float2 wv = *(const float2*)&W[k*512 + c2];
            const u64 w0 = pack2(wv.x), w1 = pack2(wv.y);
            u64 xp[10] = {xa.x, xa.y, xc.x, xc.y, xe.x, xe.y, xg.x, xg.y, xi.x, xi.y};
#pragma unroll
            for (int p = 0; p < 10; p++) {
                ffma2(acc[p][0], xp[p], w0);
                ffma2(acc[p][1], xp[p], w1);
            }
        }
        float* outp = isL ? s_XL : s_XR;
#pragma unroll
        for (int p = 0; p < 10; p++) {
            *(u64*)&outp[p*1024 + c2*2]     = acc[p][0];
            *(u64*)&outp[p*1024 + (c2+1)*2] = acc[p][1];
        }
    }
    __syncthreads();

    // ---- logits: 8-lane subgroups, 4 tasks/warp, 16 warps => 2 rounds ----
    {
        const int warp = t >> 5, lane = t & 31;
        const int sub = lane >> 3, l8 = lane & 7;
#pragma unroll 1
        for (int rr = 0; rr < 2; rr++) {
            const int task = rr*64 + warp*4 + sub;
            if (task < 80) {
                const int g = task / 40;
                const int hj = task % 40;
                const int h = hj / 10, j = hj % 10;
                const int jp = j >> 1, pj = j & 1;
                float s[10];
#pragma unroll
                for (int i = 0; i < 10; i++) s[i] = 0.f;
#pragma unroll
                for (int cc = 0; cc < 4; cc++) {
                    const int c = l8*4 + cc*32;
                    const int cbase = (h*128 + c)*2;
                    const float4 r0 = *(const float4*)&s_XR[(g*5 + jp)*1024 + cbase];
                    const float4 r1 = *(const float4*)&s_XR[(g*5 + jp)*1024 + cbase + 4];
                    const float xr0 = pj ? r0.y : r0.x;
                    const float xr1 = pj ? r0.w : r0.z;
                    const float xr2 = pj ? r1.y : r1.x;
                    const float xr3 = pj ? r1.w : r1.z;
                    const float4 at = *(const float4*)&s_att[h*128 + c];
#pragma unroll
                    for (int ip = 0; ip < 5; ip++) {
                        const float4 a = *(const float4*)&s_XL[(g*5 + ip)*1024 + cbase];
                        const float4 b = *(const float4*)&s_XL[(g*5 + ip)*1024 + cbase + 4];
                        float e0 = a.x + xr0;
                        float e1 = a.z + xr1;
                        float e2 = b.x + xr2;
                        float e3 = b.z + xr3;
                        float v =        at.x * fmaf(e0, 0.6f, 0.4f*fabsf(e0));
                        v = fmaf(at.y, fmaf(e1, 0.6f, 0.4f*fabsf(e1)), v);
                        v = fmaf(at.z, fmaf(e2, 0.6f, 0.4f*fabsf(e2)), v);
                        v = fmaf(at.w, fmaf(e3, 0.6f, 0.4f*fabsf(e3)), v);
                        s[2*ip] += v;
                        e0 = a.y + xr0;
                        e1 = a.w + xr1;
                        e2 = b.y + xr2;
                        e3 = b.w + xr3;
                        v =        at.x * fmaf(e0, 0.6f, 0.4f*fabsf(e0));
                        v = fmaf(at.y, fmaf(e1, 0.6f, 0.4f*fabsf(e1)), v);
                        v = fmaf(at.z, fmaf(e2, 0.6f, 0.4f*fabsf(e2)), v);
                        v = fmaf(at.w, fmaf(e3, 0.6f, 0.4f*fabsf(e3)), v);
                        s[2*ip+1] += v;
                    }
                }
#pragma unroll
                for (int i = 0; i < 10; i++) {
                    s[i] += __shfl_xor_sync(0xffffffffu, s[i], 4);
                    s[i] += __shfl_xor_sync(0xffffffffu, s[i], 2);
                    s[i] += __shfl_xor_sync(0xffffffffu, s[i], 1);
                }
                if (l8 == 0) {
#pragma unroll
                    for (int i = 0; i < 10; i++) s_log[g*640 + hj*16 + i] = s[i];
                }
            }
        }
    }
    __syncthreads();

    // ---- softmax over i per (g,h,j) ----
    if (t < 80) {
        float* lg = s_log + (t / 40)*640 + (t % 40)*16;
        float m = lg[0];
#pragma unroll
        for (int i = 1; i < 10; i++) m = fmaxf(m, lg[i]);
        float a[10]; float sum = 0.f;
#pragma unroll
        for (int i = 0; i < 10; i++) { a[i] = __expf(lg[i] - m); sum += a[i]; }
        const float inv = __fdividef(1.f, sum);
#pragma unroll
        for (int i = 0; i < 10; i++) lg[i] = a[i] * inv;
    }
    __syncthreads();

    // ---- aggregate: out[j,c] = bias + 0.25 * sum_h sum_i alpha*XL ----
    // 512 threads: c = t&127, q = t>>7 -> (g, half-of-j)
    {
        const int c = t & 127, q = t >> 7;
        const int g = q >> 1, jh = q & 1;
        const float bv = bias[c];
        float accj[5] = {0.f, 0.f, 0.f, 0.f, 0.f};
#pragma unroll
        for (int h = 0; h < 4; h++) {
            float xlh[10];
#pragma unroll
            for (int ip = 0; ip < 5; ip++) {
                const float2 xp2 = *(const float2*)&s_XL[(g*5 + ip)*1024 + (h*128 + c)*2];
                xlh[2*ip] = xp2.x; xlh[2*ip+1] = xp2.y;
            }
#pragma unroll
            for (int jj = 0; jj < 5; jj++) {
                const float* al = s_log + g*640 + (h*10 + jh*5 + jj)*16;
                const float4 a0 = *(const float4*)al;
                const float4 a1 = *(const float4*)(al + 4);
                const float2 a2 = *(const float2*)(al + 8);
                float v = accj[jj];
                v = fmaf(a0.x, xlh[0], v); v = fmaf(a0.y, xlh[1], v);
                v = fmaf(a0.z, xlh[2], v); v = fmaf(a0.w, xlh[3], v);
                v = fmaf(a1.x, xlh[4], v); v = fmaf(a1.y, xlh[5], v);
                v = fmaf(a1.z, xlh[6], v); v = fmaf(a1.w, xlh[7], v);
                v = fmaf(a2.x, xlh[8], v); v = fmaf(a2.y, xlh[9], v);
                accj[jj] = v;
            }
        }
#pragma unroll
        for (int jj = 0; jj < 5; jj++) {
            const int r = g*10 + jh*5 + jj;
            float v = accj[jj]*0.25f + bv;
            if (accum) v += s_out[c*RWS + r];
            s_out[c*RWS + r] = v;
        }
    }
    __syncthreads();
}

// ======================= CGConv relation =======================
// F bufs in s_F: Fd@0, Fs@2560, Sd@5120, Ss@7680; pair-interleaved [p][c][par]
__device__ __forceinline__ void cgconv_block(
    const float* __restrict__ s_src, const float* __restrict__ s_dst,
    const float* __restrict__ Wf, const float* __restrict__ bf,
    const float* __restrict__ Ws, const float* __restrict__ bs,
    float* s_F, float* s_out, bool accum)
{
    const int t = threadIdx.x;
    {
        const int fs   = t >> 8;            // 0: f-branch, 1: s-branch
        const int half = (t >> 7) & 1;      // 0: dst rows of W, 1: src rows
        const int c    = t & 127;
        const float* __restrict__ W  = (fs ? Ws : Wf) + half*Hd*Hd;
        const float* __restrict__ xb = half ? s_src : s_dst;
        u64 acc[10];
#pragma unroll
        for (int p = 0; p < 10; p++) acc[p] = 0ull;
#pragma unroll 2
        for (int k = 0; k < Hd; k++) {
            const ulonglong2 xa = *(const ulonglong2*)&xb[k*RWS + 0];
            const ulonglong2 xc = *(const ulonglong2*)&xb[k*RWS + 4];
            const ulonglong2 xe = *(const ulonglong2*)&xb[k*RWS + 8];
            const ulonglong2 xg = *(const ulonglong2*)&xb[k*RWS + 12];
            const ulonglong2 xi = *(const ulonglong2*)&xb[k*RWS + 16];
            const u64 w = pack2(W[k*Hd + c]);
            u64 xp[10] = {xa.x, xa.y, xc.x, xc.y, xe.x, xe.y, xg.x, xg.y, xi.x, xi.y};
#pragma unroll
            for (int p = 0; p < 10; p++) ffma2(acc[p], xp[p], w);
        }
        if (half == 0) {   // fold bias into dst half
            const u64 bv = pack2((fs ? bs : bf)[c]);
#pragma unroll
            for (int p = 0; p < 10; p++) acc[p] = fadd2(acc[p], bv);
        }
        float* F = s_F + fs*5120 + half*2560;
#pragma unroll
        for (int p = 0; p < 10; p++)
            *(u64*)&F[p*256 + c*2] = acc[p];
    }
    __syncthreads();

    // ---- elementwise: out_i = x_i + sum_j sigmoid(Fd_i+Fs_j)*softplus(Sd_i+Ss_j)
    {
        const int c = t & 127, q = t >> 7;
        const int g = q >> 1, ih = q & 1;
        const float* Fd = s_F;
        const float* Fs = s_F + 2560;
        const float* Sd = s_F + 5120;
        const float* Ss = s_F + 7680;
        float fsv[10], ssv[10];
#pragma unroll
        for (int jp = 0; jp < 5; jp++) {
            const float2 f2 = *(const float2*)&Fs[(g*5 + jp)*256 + c*2];
            const float2 s2 = *(const float2*)&Ss[(g*5 + jp)*256 + c*2];
            fsv[2*jp] = f2.x; fsv[2*jp+1] = f2.y;
            ssv[2*jp] = s2.x; ssv[2*jp+1] = s2.y;
        }
#pragma unroll
        for (int jj = 0; jj < 5; jj++) {
            const int i = ih*5 + jj;
            const int r = g*10 + i;
            const float fd = Fd[(g*5 + (i>>1))*256 + c*2 + (i&1)];
            const float sd = Sd[(g*5 + (i>>1))*256 + c*2 + (i&1)];
            float acc = s_dst[c*RWS + r];   // residual
#pragma unroll
            for (int j = 0; j < 10; j++) {
                const float f = fd + fsv[j];
                const float s = sd + ssv[j];
                const float sig = __fdividef(1.f, 1.f + __expf(-f));
                const float sp  = fmaxf(s, 0.f) + __logf(1.f + __expf(-fabsf(s)));
                acc = fmaf(sig, sp, acc);
            }
            if (accum) acc += s_out[c*RWS + r];
            s_out[c*RWS + r] = acc;
        }
    }
    __syncthreads();
}

// ======================= node linear (both matrices, split-k=2) ===============
__device__ __forceinline__ void dual_linear_block(
    const float* __restrict__ s_nm, const float* __restrict__ s_no,
    const float* __restrict__ W, const float* __restrict__ b,
    float* s_xm, float* s_xo, float* s_stage)
{
    const int t = threadIdx.x;
    const int kh  = t >> 8;
    const int sel = (t >> 7) & 1;
    const int c   = t & 127;
    const int id  = sel*128 + c;
    const float* __restrict__ xb = sel ? s_no : s_nm;
    u64 acc[10];
#pragma unroll
    for (int p = 0; p < 10; p++) acc[p] = 0ull;
    const int kbase = kh * 64;
#pragma unroll 2
    for (int kk = 0; kk < 64; kk++) {
        const int k = kbase + kk;
        const ulonglong2 xa = *(const ulonglong2*)&xb[k*RWS + 0];
        const ulonglong2 xc = *(const ulonglong2*)&xb[k*RWS + 4];
        const ulonglong2 xe = *(const ulonglong2*)&xb[k*RWS + 8];
        const ulonglong2 xg = *(const ulonglong2*)&xb[k*RWS + 12];
        const ulonglong2 xi = *(const ulonglong2*)&xb[k*RWS + 16];
        const u64 w = pack2(W[k*Hd + c]);
        u64 xp[10] = {xa.x, xa.y, xc.x, xc.y, xe.x, xe.y, xg.x, xg.y, xi.x, xi.y};
#pragma unroll
        for (int p = 0; p < 10; p++) ffma2(acc[p], xp[p], w);
    }
    u64* stage = (u64*)s_stage;
    if (kh == 1) {
#pragma unroll
        for (int p = 0; p < 10; p++) stage[id*10 + p] = acc[p];
    }
    __syncthreads();
    if (kh == 0) {
        const u64 bv = pack2(b[c]);
        float* outp = sel ? s_xo : s_xm;
#pragma unroll
        for (int p = 0; p < 10; p++)
            *(u64*)&outp[c*RWS + 2*p] = fadd2(fadd2(acc[p], stage[id*10 + p]), bv);
    }
    __syncthreads();
}

extern "C" __global__ void __launch_bounds__(TPB, 1)
yomi_kernel(
    const float* __restrict__ x_my,  const float* __restrict__ x_opp,
    const float* __restrict__ W_enc, const float* __restrict__ b_enc,
    const float* __restrict__ gb_Wl, const float* __restrict__ gb_Wr,
    const float* __restrict__ gb_att,const float* __restrict__ gb_b,
    const float* __restrict__ gr_Wl, const float* __restrict__ gr_Wr,
    const float* __restrict__ gr_att,const float* __restrict__ gr_b,
    const float* __restrict__ cl_Wf, const float* __restrict__ cl_bf,
    const float* __restrict__ cl_Ws, const float* __restrict__ cl_bs,
    const float* __restrict__ cr_Wf, const float* __restrict__ cr_bf,
    const float* __restrict__ cr_Ws, const float* __restrict__ cr_bs,
    const float* __restrict__ node_W,const float* __restrict__ node_b,
    const float* __restrict__ W1,    const float* __restrict__ b1,
    const float* __restrict__ W2,    const float* __restrict__ b2,
    float* __restrict__ out)
{
    extern __shared__ float sm[];
    float* s_xm  = sm + OFF_XM;
    float* s_xo  = sm + OFF_XO;
    float* s_nm  = sm + OFF_NM;
    float* s_no  = sm + OFF_NO;
    float* s_A   = sm + OFF_A;
    float* s_B   = sm + OFF_B;
    float* s_att = sm + OFF_ATT;
    float* s_log = sm + OFF_LOG;
    float* s_pool= sm + OFF_POOL;
    float* s_red = sm + OFF_RED;

    const int blk = blockIdx.x;
    const int t = threadIdx.x;

    // ---- encoder: stage transposed raw x, then [20,32]@[32,128]+b per matrix
    {
        for (int idx = t; idx < 2*RWS*CDm; idx += TPB) {
            const int m = idx / (RWS*CDm);
            const int rem = idx - m*RWS*CDm;
            const int r20 = rem / CDm, k = rem % CDm;
            const float v = (m ? x_opp : x_my)[(blk*RWS + r20)*CDm + k];
            s_A[m*640 + k*RWS + r20] = v;
        }
        __syncthreads();
        // 512 threads: c = t&127, m = (t>>7)&1, gh = t>>8 picks graph (5 pairs)
        const int c = t & 127, m = (t >> 7) & 1, gh = t >> 8;
        const float* xb = s_A + m*640;
        u64 acc[5];
#pragma unroll
        for (int p = 0; p < 5; p++) acc[p] = 0ull;
#pragma unroll 4
        for (int k = 0; k < CDm; k++) {
            const u64 w = pack2(W_enc[k*Hd + c]);
#pragma unroll
            for (int p = 0; p < 5; p++) {
                const u64 xp = *(const u64*)&xb[k*RWS + gh*10 + 2*p];
                ffma2(acc[p], xp, w);
            }
        }
        const u64 bv = pack2(b_enc[c]);
        float* outp = m ? s_xo : s_xm;
#pragma unroll
        for (int p = 0; p < 5; p++)
            *(u64*)&outp[c*RWS + gh*10 + 2*p] = fadd2(acc[p], bv);
        __syncthreads();
    }

    // ---- 2 hetero layers ----
#pragma unroll 1
    for (int l = 0; l < 2; l++) {
        const int wG = l * Hd * 512;
        const int wC = l * 2*Hd * Hd;
        const int wN = l * Hd * Hd;
        const int wb = l * Hd;
        gatv2_block(s_xm, s_xo, gb_Wl + wG, gb_Wr + wG, gb_att + l*4*Hd,
                    gb_b + wb, s_A, s_B, s_att, s_log, s_no, false);
        cgconv_block(s_xm, s_xo, cl_Wf + wC, cl_bf + wb, cl_Ws + wC, cl_bs + wb,
                     s_A, s_no, true);
        cgconv_block(s_xo, s_xm, cr_Wf + wC, cr_bf + wb, cr_Ws + wC, cr_bs + wb,
                     s_A, s_nm, false);
        gatv2_block(s_xo, s_xm, gr_Wl + wG, gr_Wr + wG, gr_att + l*4*Hd,
                    gr_b + wb, s_A, s_B, s_att, s_log, s_nm, true);
        dual_linear_block(s_nm, s_no, node_W + wN, node_b + wb, s_xm, s_xo, s_A);
    }

    // ---- pool + MLP head (per graph) ----
    {
        const int c = t & 127, m = (t >> 7) & 1, gh = t >> 8;
        const float* xb = m ? s_xo : s_xm;
        float p = 0.f;
#pragma unroll
        for (int r = 0; r < NPH; r++) p += xb[c*RWS + gh*10 + r];
        s_pool[gh*256 + m*128 + c] = p * 0.1f;
    }
    __syncthreads();
    {
        // W1 GEMM, split-k=2: c = t&127, g = (t>>7)&1, kh = t>>8
        const int c = t & 127, g = (t >> 7) & 1, kh = t >> 8;
        float a = 0.f;
#pragma unroll 4
        for (int kk = 0; kk < 128; kk++) {
            const int k = kh*128 + kk;
            a = fmaf(s_pool[g*256 + k], W1[k*Hd + c], a);
        }
        s_red[t] = a;
    }
    __syncthreads();
    if (t < 256) {
        const int c = t & 127;
        float hv = s_red[t] + s_red[t + 256] + b1[c];
        hv = (hv >= 0.f) ? hv : 128.f * hv;   // LeakyReLU slope = final_dim
        s_red[t] = hv * W2[c];
    }
    __syncthreads();
    if (t < 64) {
        const int g = t >> 5, lane = t & 31;
        float v = s_red[g*128 + lane] + s_red[g*128 + lane + 32]
                + s_red[g*128 + lane + 64] + s_red[g*128 + lane + 96];
#pragma unroll
        for (int o = 16; o > 0; o >>= 1) v += __shfl_xor_sync(0xffffffffu, v, o);
        if (lane == 0) out[blk*G + g] = v + b2[0];
    }
}

extern "C" void kernel_launch(void* const* d_in, const int* in_sizes, int n_in,
                              void* d_out, int out_size)
{
    const float* x_my   = (const float*)d_in[0];
    const float* x_opp  = (const float*)d_in[1];
    const float* W_enc  = (const float*)d_in[2];
    const float* b_enc  = (const float*)d_in[3];
    const float* gb_Wl  = (const float*)d_in[4];
    const float* gb_Wr  = (const float*)d_in[5];
    const float* gb_att = (const float*)d_in[6];
    const float* gb_b   = (const float*)d_in[7];
    const float* gr_Wl  = (const float*)d_in[8];
    const float* gr_Wr  = (const float*)d_in[9];
    const float* gr_att = (const float*)d_in[10];
    const float* gr_b   = (const float*)d_in[11];
    const float* cl_Wf  = (const float*)d_in[12];
    const float* cl_bf  = (const float*)d_in[13];
    const float* cl_Ws  = (const float*)d_in[14];
    const float* cl_bs  = (const float*)d_in[15];
    const float* cr_Wf  = (const float*)d_in[16];
    const float* cr_bf  = (const float*)d_in[17];
    const float* cr_Ws  = (const float*)d_in[18];
    const float* cr_bs  = (const float*)d_in[19];
    const float* node_W = (const float*)d_in[20];
    const float* node_b = (const float*)d_in[21];
    const float* W1     = (const float*)d_in[22];
    const float* b1     = (const float*)d_in[23];
    const float* W2     = (const float*)d_in[24];
    const float* b2     = (const float*)d_in[25];

    const int n_nodes = in_sizes[0] / CDm;   // N = B * NPH
    const int nblocks = n_nodes / (NPH * G); // B / 2

    cudaFuncSetAttribute(yomi_kernel,
                         cudaFuncAttributeMaxDynamicSharedMemorySize, SMEM_BYTES);

    yomi_kernel<<<nblocks, TPB, SMEM_BYTES>>>(
        x_my, x_opp, W_enc, b_enc,
        gb_Wl, gb_Wr, gb_att, gb_b,
        gr_Wl, gr_Wr, gr_att, gr_b,
        cl_Wf, cl_bf, cl_Ws, cl_bs,
        cr_Wf, cr_bf, cr_Ws, cr_bs,
        node_W, node_b, W1, b1, W2, b2,
        (float*)d_out);
}